// round 5
// baseline (speedup 1.0000x reference)
#include <cuda_runtime.h>
#include <cuda_bf16.h>

// CRF forward in scaled-probability domain, smem-broadcast recurrence.
//
//   feats      : (512, 1024, 32) f32
//   mask       : (512, 1024)     f32   (0/1 semantics)
//   transition : (32, 32)        f32
//   out        : (1024,)         f32
//
// alpha_t[j] = feat[t,b,j] + logsumexp_i(alpha_{t-1}[i] + T[j,i])
// With p = exp(alpha - M), E = exp(T):  q = E p ; p' = q * exp(feat)
// Renormalize by max(p) every 8 steps (fp32 range covers 8 unchecked steps:
// worst growth ~1.2e4^8 = 1e33 < 3.4e38), M += log(max).
// out[b] = M + log( sum_j p[j] * exp(T[END,j]) ).
//
// Mapping: ONE batch per warp, lane = tag. 1024 warps = 128 blocks x 256 thr
// => 2 warps per SMSP (latency hiding). p broadcast via double-buffered smem:
// per step 1 STS.32 + 1 syncwarp + 8 broadcast LDS.128 (no shuffles).
// exp(feat) computed at prefetch time, 8 steps ahead of use.

#define SEQ   512
#define BATCH 1024
#define TAGS  32
#define START_TAG 30
#define END_TAG   31
#define WPB   8                       // warps per block
#define TPB   (WPB * 32)              // 256
#define NBLOCKS (BATCH / WPB)         // 128

__global__ __launch_bounds__(TPB, 1)
void crf_fwd_kernel(const float* __restrict__ feats,
                    const float* __restrict__ mask,
                    const float* __restrict__ trans,
                    float* __restrict__ out)
{
    const int lane = threadIdx.x & 31;     // tag index j
    const int w    = threadIdx.x >> 5;     // warp in block
    const int b    = blockIdx.x * WPB + w; // batch for this warp
    const int j    = lane;

    __shared__ float sp[WPB][2][TAGS];     // double-buffered p per warp

    // ---- E row j in registers --------------------------------------------
    float e[TAGS];
#pragma unroll
    for (int i = 0; i < TAGS; ++i)
        e[i] = __expf(trans[j * TAGS + i]);
    const float eEnd = __expf(trans[END_TAG * TAGS + j]);

    // ---- init ------------------------------------------------------------
    float p = (j == START_TAG) ? 1.0f : 0.0f;
    float M = 0.0f;
    sp[w][0][j] = p;                       // step 0 reads buffer 0

    // ---- prefetch ring: ef = exp(feat) computed 8 steps ahead ------------
    const int fbase = b * TAGS + j;        // lane-contiguous: 128B per warp
    float efr[8], mr[8];
#pragma unroll
    for (int u = 0; u < 8; ++u) {
        efr[u] = __expf(feats[u * (BATCH * TAGS) + fbase]);
        mr[u]  = mask[u * BATCH + b];
    }
    __syncwarp();

    // ---- main recurrence -------------------------------------------------
    for (int blk = 0; blk < SEQ / 8; ++blk) {
        const int t0 = blk * 8;

#pragma unroll
        for (int u = 0; u < 8; ++u) {
            const float ef = efr[u];
            const float m  = mr[u];

            // prefetch t+8 (wraps harmlessly on the final block)
            const int tp = (t0 + 8 + u) & (SEQ - 1);
            efr[u] = __expf(feats[tp * (BATCH * TAGS) + fbase]);
            mr[u]  = mask[tp * BATCH + b];

            // make previous step's STS visible to all lanes
            __syncwarp();

            // q[j] = sum_i e[i] * p[i] via 8 broadcast LDS.128
            const float4* __restrict__ src =
                reinterpret_cast<const float4*>(sp[w][u & 1]);
            float a0 = 0.f, a1 = 0.f, a2 = 0.f, a3 = 0.f;
#pragma unroll
            for (int h = 0; h < 8; ++h) {
                const float4 v = src[h];
                a0 = fmaf(e[4 * h + 0], v.x, a0);
                a1 = fmaf(e[4 * h + 1], v.y, a1);
                a2 = fmaf(e[4 * h + 2], v.z, a2);
                a3 = fmaf(e[4 * h + 3], v.w, a3);
            }
            const float q = (a0 + a1) + (a2 + a3);
            const float r = q * ef;
            p = (m != 0.0f) ? r : p;       // 0/1 mask select

            // renormalize at the end of each 8-step block
            if (u == 7) {
                float s = p;
#pragma unroll
                for (int off = 16; off > 0; off >>= 1)
                    s = fmaxf(s, __shfl_xor_sync(0xffffffffu, s, off));
                const float inv = 1.0f / s;
                p *= inv;
                M += __logf(s);
            }

            sp[w][(u + 1) & 1][j] = p;     // write for next step
        }
    }

    // ---- epilogue --------------------------------------------------------
    float acc = p * eEnd;
#pragma unroll
    for (int off = 16; off > 0; off >>= 1)
        acc += __shfl_xor_sync(0xffffffffu, acc, off);

    if (lane == 0)
        out[b] = M + __logf(acc);
}

extern "C" void kernel_launch(void* const* d_in, const int* in_sizes, int n_in,
                              void* d_out, int out_size)
{
    const float* feats = (const float*)d_in[0];
    const float* msk   = (const float*)d_in[1];
    const float* trans = (const float*)d_in[2];
    float*       o     = (float*)d_out;

    crf_fwd_kernel<<<NBLOCKS, TPB>>>(feats, msk, trans, o);
}